// round 1
// baseline (speedup 1.0000x reference)
#include <cuda_runtime.h>
#include <cuda_bf16.h>

// Problem shape (fixed by the reference):
//   pred, true: [B=2, C=16, D=64, H=128, W=128] f32
//   weight:     [C=16] f32
//   out:        scalar f32
//
// result = sum_c( w[c] * mean_{b,d,h,w}(bce) ) / sum_c(w[c])
//        = ( sum over all elements of w[class(i)] * bce_i ) / (sum_w * B*D*H*W)
//
// Layout [B,C,D,H,W]: each contiguous SPATIAL=D*H*W=1,048,576-element segment
// belongs to a single class c = seg % C. We assign blocks to segments so the
// class weight is applied once per block.

#define SPATIAL   (64 * 128 * 128)      // 1,048,576 elements per (b,c) segment
#define N_SEGS    (2 * 16)              // B*C = 32 segments
#define C_CLASSES 16
#define BLOCKS_PER_SEG 32
#define THREADS   256
#define F4_PER_SEG (SPATIAL / 4)        // 262,144 float4 per segment
#define F4_PER_BLOCK (F4_PER_SEG / BLOCKS_PER_SEG)  // 8,192 float4 per block
// => per-thread: 8192/256 = 32 float4 = 128 elements. Float partial sums are
//    accurate enough (|bce| <= 100, 128-term sum; block partial promoted to
//    double before the global atomic).

__device__ double g_acc;

__global__ void zero_acc_kernel() { g_acc = 0.0; }

__device__ __forceinline__ float bce_elem(float p, float t) {
    // torch F.binary_cross_entropy: clamp log terms at -100
    float lp  = fmaxf(__logf(p), -100.0f);
    float l1  = fmaxf(__logf(1.0f - p), -100.0f);
    // -(t*lp + (1-t)*l1) = -(t*(lp - l1) + l1)
    return -fmaf(t, lp - l1, l1);
}

__global__ __launch_bounds__(THREADS)
void bce_reduce_kernel(const float4* __restrict__ pred,
                       const float4* __restrict__ tru,
                       const float*  __restrict__ weight) {
    const int seg = blockIdx.x / BLOCKS_PER_SEG;
    const int sub = blockIdx.x % BLOCKS_PER_SEG;
    const size_t base = (size_t)seg * F4_PER_SEG + (size_t)sub * F4_PER_BLOCK;

    float acc = 0.0f;
    #pragma unroll 4
    for (int i = threadIdx.x; i < F4_PER_BLOCK; i += THREADS) {
        float4 p = __ldg(&pred[base + i]);
        float4 t = __ldg(&tru[base + i]);
        acc += bce_elem(p.x, t.x);
        acc += bce_elem(p.y, t.y);
        acc += bce_elem(p.z, t.z);
        acc += bce_elem(p.w, t.w);
    }

    // warp reduce
    #pragma unroll
    for (int off = 16; off > 0; off >>= 1)
        acc += __shfl_xor_sync(0xFFFFFFFFu, acc, off);

    __shared__ float warp_sums[THREADS / 32];
    const int lane = threadIdx.x & 31;
    const int wid  = threadIdx.x >> 5;
    if (lane == 0) warp_sums[wid] = acc;
    __syncthreads();

    if (wid == 0) {
        float v = (lane < THREADS / 32) ? warp_sums[lane] : 0.0f;
        #pragma unroll
        for (int off = 4; off > 0; off >>= 1)
            v += __shfl_xor_sync(0xFFFFFFFFu, v, off);
        if (lane == 0) {
            const float w = weight[seg % C_CLASSES];
            atomicAdd(&g_acc, (double)v * (double)w);
        }
    }
}

__global__ void finalize_kernel(const float* __restrict__ weight, float* __restrict__ out) {
    double sum_w = 0.0;
    #pragma unroll
    for (int c = 0; c < C_CLASSES; c++) sum_w += (double)weight[c];
    const double denom = sum_w * (double)(2.0 * 64.0 * 128.0 * 128.0); // B*D*H*W
    out[0] = (float)(g_acc / denom);
}

extern "C" void kernel_launch(void* const* d_in, const int* in_sizes, int n_in,
                              void* d_out, int out_size) {
    const float4* pred = (const float4*)d_in[0];
    const float4* tru  = (const float4*)d_in[1];
    const float*  w    = (const float*)d_in[2];
    float* out = (float*)d_out;

    zero_acc_kernel<<<1, 1>>>();
    bce_reduce_kernel<<<N_SEGS * BLOCKS_PER_SEG, THREADS>>>(pred, tru, w);
    finalize_kernel<<<1, 1>>>(w, out);
}